// round 14
// baseline (speedup 1.0000x reference)
#include <cuda_runtime.h>
#include <cuda_bf16.h>
#include <math.h>
#include <stdint.h>

#define H 1024
#define L 4096
#define V 50257
#define G3 3072
#define X2 2048
#define NPART 8
#define VP 50432           // 197*256
#define CTXP 128           // ctx partial chunks

// ---------------- scratch (device globals, no allocation) ----------------
__device__ __nv_bfloat16 g_encb[L * H];   // bf16 enc, row-major [l][h]
__device__ uint32_t g_wkbT[H * (H / 2)];  // Wk bf16x2, TRANSPOSED: [n][k2]
__device__ float g_qwp[32 * H];           // qW partials
__device__ float g_scorep[NPART * L];     // [bn][l] partial scores
__device__ float g_attn[L];               // UNNORMALIZED exp(s)
__device__ float g_invS;                  // 1/sum(exp)
__device__ float g_ctxp[CTXP * H];        // context partials
__device__ float g_x[X2];                 // concat(context, relu(emb))
__device__ float g_gi0[G3], g_gh0[G3];    // GRU layer-0 gates
__device__ float g_gi1[G3], g_gh1[G3];    // GRU layer-1 gates
__device__ float g_logitp[4 * VP];        // split-K logits partials
__device__ float g_mpart[256];
__device__ float g_spart[256];

__device__ __forceinline__ float sigmoidf_(float x) { return 1.0f / (1.0f + expf(-x)); }

__device__ __forceinline__ uint32_t pk(float lo, float hi) {
    __nv_bfloat162 v = __floats2bfloat162_rn(lo, hi);
    return *(uint32_t*)&v;
}

__device__ __forceinline__ void mma_bf16(float c[4], const uint32_t a[4],
                                         uint32_t b0, uint32_t b1) {
    asm volatile(
        "mma.sync.aligned.m16n8k16.row.col.f32.bf16.bf16.f32 "
        "{%0,%1,%2,%3}, {%4,%5,%6,%7}, {%8,%9}, {%0,%1,%2,%3};"
        : "+f"(c[0]), "+f"(c[1]), "+f"(c[2]), "+f"(c[3])
        : "r"(a[0]), "r"(a[1]), "r"(a[2]), "r"(a[3]), "r"(b0), "r"(b1));
}

__device__ __forceinline__ void ldsm4(uint32_t& r0, uint32_t& r1, uint32_t& r2,
                                      uint32_t& r3, uint32_t addr) {
    asm volatile("ldmatrix.sync.aligned.m8n8.x4.shared.b16 {%0,%1,%2,%3}, [%4];"
                 : "=r"(r0), "=r"(r1), "=r"(r2), "=r"(r3) : "r"(addr));
}

__device__ __forceinline__ void cpa16(uint32_t dst, const void* src) {
    asm volatile("cp.async.cg.shared.global [%0], [%1], 16;\n"
                 :: "r"(dst), "l"(__cvta_generic_to_global(src)));
}

// ---------------- K0: fused prep (cvt_enc | cvt_wk | qw_partial) ---------------
__global__ void k_prep(const float* __restrict__ enc, const float* __restrict__ Wk,
                       const float* __restrict__ hidden, const float* __restrict__ Wq) {
    int b = blockIdx.x;
    int tid = threadIdx.x;
    if (b < 4096) {
        int idx = (b * 256 + tid) * 4;
        float4 v = *(const float4*)(enc + idx);
        uint2 o = make_uint2(pk(v.x, v.y), pk(v.z, v.w));
        *(uint2*)&g_encb[idx] = o;
    } else if (b < 4608) {
        int idx = (b - 4096) * 256 + tid;   // 0..131071
        int n = idx & 1023;
        int k2q = idx >> 10;
        uint4 o;
        const float* c = Wk + (size_t)(8 * k2q) * H + n;
        o.x = pk(c[0],     c[H]);
        o.y = pk(c[2 * H], c[3 * H]);
        o.z = pk(c[4 * H], c[5 * H]);
        o.w = pk(c[6 * H], c[7 * H]);
        *(uint4*)&g_wkbT[(size_t)n * 512 + k2q * 4] = o;
    } else {
        int r = b - 4608;                   // 0..127
        int j = (r & 3) * 256 + tid;
        int i0 = (r >> 2) * 32;
        const float* q = hidden + H;
        float acc = 0.f;
#pragma unroll
        for (int i = 0; i < 32; i++)
            acc += q[i0 + i] * Wq[(size_t)(i0 + i) * H + j];
        g_qwp[(r >> 2) * H + j] = acc;
    }
}

// ---------------- K3: attention GEMM, bf16+LDSM, BK=64, 3-stage ----------------
// BM=128, BN=128; grid (8 bn, 32 bm); 8 warps = 2m x 4n; warp 64x32.
// Rows stored 144B (36 u32) for conflict-free LDSM. Slab = 64 k (18432 B/side).
// smem BYTES: A stage s @ s*18432 | B stage s @ 55296 + s*18432 |
//   sqw @110592 (512B) | swv @111104 (512B)  => total 111616
#define GEMM_SMEM_BYTES 111616
__global__ void __launch_bounds__(256, 2)
k_attn_gemm(const float* __restrict__ wv) {
    extern __shared__ uint32_t sm[];
    const int tid = threadIdx.x;
    const int warp = tid >> 5, lane = tid & 31;
    const int wm = warp & 1, wn = warp >> 1;     // 2 m x 4 n
    const int g = lane >> 2, t = lane & 3;
    const int bn = blockIdx.x, bm = blockIdx.y;

    float* sqw = (float*)((char*)sm + 110592);
    float* swv = (float*)((char*)sm + 111104);

    if (tid < 128) {
        int col = bn * 128 + tid;
        float s = 0.f;
#pragma unroll
        for (int p = 0; p < 32; p++) s += g_qwp[p * H + col];
        sqw[tid] = s;
        swv[tid] = wv[col];
    }

    float acc[4][4][4];
#pragma unroll
    for (int mt = 0; mt < 4; mt++)
#pragma unroll
        for (int nt = 0; nt < 4; nt++)
#pragma unroll
            for (int i = 0; i < 4; i++) acc[mt][nt][i] = 0.f;

    // producers: row = tid>>1, half = tid&1 covers 32 k floats (64B)
    const int prow = tid >> 1, part = tid & 1;
    const __nv_bfloat16* Ag = g_encb + (size_t)(bm * 128 + prow) * H + part * 32;
    const uint32_t* Bg = g_wkbT + (size_t)(bn * 128 + prow) * 512 + part * 16;
    const uint32_t smBase = (uint32_t)__cvta_generic_to_shared(sm);
    const uint32_t aDst = smBase + (uint32_t)(prow * 144 + part * 64);
    const uint32_t bDst = smBase + 55296u + (uint32_t)(prow * 144 + part * 64);

#define LOAD_STAGE(it, st)                                               \
    {                                                                    \
        const uint32_t so = (uint32_t)(st) * 18432u;                     \
        const __nv_bfloat16* as_ = Ag + (size_t)(it) * 64;               \
        cpa16(aDst + so,      as_);                                      \
        cpa16(aDst + so + 16, as_ + 8);                                  \
        cpa16(aDst + so + 32, as_ + 16);                                 \
        cpa16(aDst + so + 48, as_ + 24);                                 \
        const uint32_t* bs_ = Bg + (size_t)(it) * 32;                    \
        cpa16(bDst + so,      bs_);                                      \
        cpa16(bDst + so + 16, bs_ + 4);                                  \
        cpa16(bDst + so + 32, bs_ + 8);                                  \
        cpa16(bDst + so + 48, bs_ + 12);                                 \
        asm volatile("cp.async.commit_group;");                          \
    }

    const uint32_t lrow = lane & 15, lcol = (lane >> 4) * 4;
    uint32_t aOff[4], bOff[2];
#pragma unroll
    for (int mt = 0; mt < 4; mt++)
        aOff[mt] = smBase + ((wm * 64 + mt * 16 + lrow) * 36 + lcol) * 4;
#pragma unroll
    for (int p = 0; p < 2; p++)
        bOff[p] = smBase + 55296u + ((wn * 32 + p * 16 + lrow) * 36 + lcol) * 4;

#define COMPUTE_STAGE(st)                                                \
    {                                                                    \
        const uint32_t so = (uint32_t)(st) * 18432u;                     \
        _Pragma("unroll")                                                \
        for (int ks = 0; ks < 4; ks++) {                                 \
            const uint32_t ko = so + (uint32_t)ks * 32u;                 \
            uint32_t a[4][4];                                            \
            _Pragma("unroll")                                            \
            for (int mt = 0; mt < 4; mt++)                               \
                ldsm4(a[mt][0], a[mt][1], a[mt][2], a[mt][3], aOff[mt] + ko); \
            _Pragma("unroll")                                            \
            for (int p = 0; p < 2; p++) {                                \
                uint32_t b0e, b0o, b1e, b1o;                             \
                ldsm4(b0e, b0o, b1e, b1o, bOff[p] + ko);                 \
                _Pragma("unroll")                                        \
                for (int mt = 0; mt < 4; mt++) {                         \
                    mma_bf16(acc[mt][2 * p],     a[mt], b0e, b1e);       \
                    mma_bf16(acc[mt][2 * p + 1], a[mt], b0o, b1o);       \
                }                                                        \
            }                                                            \
        }                                                                \
    }

    LOAD_STAGE(0, 0);
    LOAD_STAGE(1, 1);

    for (int it = 0; it < 16; ++it) {
        const int st = it - (it / 3) * 3;     // it % 3
        if (it < 15) asm volatile("cp.async.wait_group 1;");
        else         asm volatile("cp.async.wait_group 0;");
        __syncthreads();
        if (it < 14) {
            const int nst = (it + 2) - ((it + 2) / 3) * 3;
            LOAD_STAGE(it + 2, nst);
        }
        COMPUTE_STAGE(st);
    }

    // epilogue: tanh(acc + qW) * wv, reduce warp's 32 cols, then across wn
    float s[8];
#pragma unroll
    for (int i = 0; i < 8; i++) s[i] = 0.f;
#pragma unroll
    for (int mt = 0; mt < 4; mt++) {
#pragma unroll
        for (int nt = 0; nt < 4; nt++) {
            int lc = wn * 32 + nt * 8 + 2 * t;
            float qw0 = sqw[lc], qw1 = sqw[lc + 1];
            float w0 = swv[lc], w1 = swv[lc + 1];
            s[mt * 2 + 0] += tanhf(acc[mt][nt][0] + qw0) * w0 + tanhf(acc[mt][nt][1] + qw1) * w1;
            s[mt * 2 + 1] += tanhf(acc[mt][nt][2] + qw0) * w0 + tanhf(acc[mt][nt][3] + qw1) * w1;
        }
    }
#pragma unroll
    for (int i = 0; i < 8; i++) {
        s[i] += __shfl_xor_sync(0xffffffffu, s[i], 1);
        s[i] += __shfl_xor_sync(0xffffffffu, s[i], 2);
    }
    __syncthreads();
    float* red = (float*)sm;
    if (t == 0) {
#pragma unroll
        for (int mt = 0; mt < 4; mt++) {
            red[(wm * 64 + mt * 16 + g) * 4 + wn]     = s[2 * mt];
            red[(wm * 64 + mt * 16 + g + 8) * 4 + wn] = s[2 * mt + 1];
        }
    }
    __syncthreads();
    if (tid < 128) {
        float vsum = red[tid * 4] + red[tid * 4 + 1] + red[tid * 4 + 2] + red[tid * 4 + 3];
        g_scorep[(size_t)bn * L + bm * 128 + tid] = vsum;
    }
}

// ---------------- K4: softmax sum (max-free: |score| <= sum|wv| ~ 16) ----------
__global__ void k_softmax() {
    __shared__ float sred[32];
    int tid = threadIdx.x;
    int wid = tid >> 5, lane = tid & 31;
    float4 v = make_float4(0.f, 0.f, 0.f, 0.f);
#pragma unroll
    for (int p = 0; p < NPART; p++) {
        float4 sp = *(const float4*)&g_scorep[(size_t)p * L + tid * 4];
        v.x += sp.x; v.y += sp.y; v.z += sp.z; v.w += sp.w;
    }
    float4 e = make_float4(expf(v.x), expf(v.y), expf(v.z), expf(v.w));
    float s = e.x + e.y + e.z + e.w;
#pragma unroll
    for (int o = 16; o > 0; o >>= 1) s += __shfl_xor_sync(0xffffffffu, s, o);
    if (lane == 0) sred[wid] = s;
    __syncthreads();
    if (wid == 0) {
        float q = sred[lane];
#pragma unroll
        for (int o = 16; o > 0; o >>= 1) q += __shfl_xor_sync(0xffffffffu, q, o);
        if (lane == 0) g_invS = 1.0f / q;
    }
    *(float4*)&g_attn[tid * 4] = e;
}

// ---------------- K5: ctx partials, bf16x2 (grid 256, 256 thr) ------------------
__global__ void k_ctx_partial() {
    int jhalf = blockIdx.x & 1;
    int lc = blockIdx.x >> 1;                 // 0..127
    int j0 = jhalf * 512 + threadIdx.x * 2;
    int l0 = lc * 32;
    float a0 = 0.f, a1 = 0.f;
#pragma unroll
    for (int l = l0; l < l0 + 32; l++) {
        float a = g_attn[l];
        __nv_bfloat162 w = *(const __nv_bfloat162*)&g_encb[(size_t)l * H + j0];
        float2 f = __bfloat1622float2(w);
        a0 += a * f.x;
        a1 += a * f.y;
    }
    g_ctxp[lc * H + j0]     = a0;
    g_ctxp[lc * H + j0 + 1] = a1;
}

// ---------------- K6: x = concat(invS * ctx, relu(emb[token])) -----------------
__global__ void k_build_x(const int* __restrict__ input, const float* __restrict__ emb) {
    int idx = blockIdx.x * 256 + threadIdx.x;
    if (idx < H) {
        float s = 0.f;
#pragma unroll
        for (int p = 0; p < CTXP; p++) s += g_ctxp[p * H + idx];
        g_x[idx] = s * g_invS;
    } else {
        int tok = input[0];
        float e = emb[(size_t)tok * H + (idx - H)];
        g_x[idx] = fmaxf(e, 0.f);
    }
}

// ---------------- K7: GRU layer-0 GEMV ----------------
__global__ void k_gru_gemv0(const float* __restrict__ Wi, const float* __restrict__ Wh,
                            const float* __restrict__ bi, const float* __restrict__ bh,
                            const float* __restrict__ hidden) {
    __shared__ float sxh[X2 + H];
    int tid = threadIdx.x;
    for (int i = tid; i < X2; i += 256) sxh[i] = g_x[i];
    for (int i = tid; i < H; i += 256) sxh[X2 + i] = hidden[i];
    __syncthreads();

    int warp = blockIdx.x * 8 + (tid >> 5);
    int lane = tid & 31;
    if (warp < G3) {
        const float* W = Wi + (size_t)warp * X2;
        float acc = 0.f;
#pragma unroll
        for (int c0 = 0; c0 < X2; c0 += 128) {
            int c = c0 + lane * 4;
            float4 w = *(const float4*)(W + c);
            acc += w.x * sxh[c] + w.y * sxh[c + 1] + w.z * sxh[c + 2] + w.w * sxh[c + 3];
        }
#pragma unroll
        for (int o = 16; o > 0; o >>= 1) acc += __shfl_down_sync(0xffffffffu, acc, o);
        if (lane == 0) g_gi0[warp] = acc + bi[warp];
    } else {
        int r = warp - G3;
        const float* W = Wh + (size_t)r * H;
        float acc = 0.f;
#pragma unroll
        for (int c0 = 0; c0 < H; c0 += 128) {
            int c = c0 + lane * 4;
            float4 w = *(const float4*)(W + c);
            acc += w.x * sxh[X2 + c] + w.y * sxh[X2 + c + 1] + w.z * sxh[X2 + c + 2] + w.w * sxh[X2 + c + 3];
        }
#pragma unroll
        for (int o = 16; o > 0; o >>= 1) acc += __shfl_down_sync(0xffffffffu, acc, o);
        if (lane == 0) g_gh0[r] = acc + bh[r];
    }
}

// ---------------- K8: GRU layer-1 GEMV, fused layer-0 combine -------------------
__global__ void k_gru_gemv1(const float* __restrict__ Wi, const float* __restrict__ Wh,
                            const float* __restrict__ bi, const float* __restrict__ bh,
                            const float* __restrict__ hidden, float* __restrict__ out_h0) {
    __shared__ float sxh[2 * H];
    int tid = threadIdx.x;
    for (int i = tid; i < H; i += 256) {
        float r = sigmoidf_(g_gi0[i] + g_gh0[i]);
        float z = sigmoidf_(g_gi0[i + H] + g_gh0[i + H]);
        float n = tanhf(g_gi0[i + 2 * H] + r * g_gh0[i + 2 * H]);
        float hn = (1.0f - z) * n + z * hidden[i];
        sxh[i] = hn;
        if (blockIdx.x == 0) out_h0[i] = hn;
        sxh[H + i] = hidden[H + i];
    }
    __syncthreads();

    int warp = blockIdx.x * 8 + (tid >> 5);
    int lane = tid & 31;
    const float* W = (warp < G3) ? (Wi + (size_t)warp * H)
                                 : (Wh + (size_t)(warp - G3) * H);
    const float* xv = (warp < G3) ? sxh : (sxh + H);
    float acc = 0.f;
#pragma unroll
    for (int c0 = 0; c0 < H; c0 += 128) {
        int c = c0 + lane * 4;
        float4 w = *(const float4*)(W + c);
        acc += w.x * xv[c] + w.y * xv[c + 1] + w.z * xv[c + 2] + w.w * xv[c + 3];
    }
#pragma unroll
    for (int o = 16; o > 0; o >>= 1) acc += __shfl_down_sync(0xffffffffu, acc, o);
    if (lane == 0) {
        if (warp < G3) g_gi1[warp] = acc + bi[warp];
        else           g_gh1[warp - G3] = acc + bh[warp - G3];
    }
}

// ---------------- K9: split-K logits partials (grid 197 x 4) -------------------
__global__ void k_logits_part(const float* __restrict__ Wd, const float* __restrict__ bd,
                              const float* __restrict__ hidden, float* __restrict__ out_h1) {
    __shared__ float sh[256];
    int tid = threadIdx.x;
    int kp = blockIdx.y;
    int i = kp * 256 + tid;
    {
        float r = sigmoidf_(g_gi1[i] + g_gh1[i]);
        float z = sigmoidf_(g_gi1[i + H] + g_gh1[i + H]);
        float n = tanhf(g_gi1[i + 2 * H] + r * g_gh1[i + 2 * H]);
        float hn = (1.0f - z) * n + z * hidden[H + i];
        sh[tid] = hn;
        if (blockIdx.x == 0) out_h1[i] = hn;
    }
    __syncthreads();

    int v = blockIdx.x * 256 + tid;
    if (v < V) {
        float acc = (kp == 0) ? bd[v] : 0.f;
        const float* Wb = Wd + (size_t)(kp * 256) * V + v;
#pragma unroll 16
        for (int h = 0; h < 256; h++)
            acc += sh[h] * Wb[(size_t)h * V];
        g_logitp[kp * VP + v] = acc;
    }
}

// ---------------- K10: combine partials + softmax stats ------------------------
__global__ void k_logits_comb(float* __restrict__ out) {
    __shared__ float sred[256];
    int tid = threadIdx.x;
    int v = blockIdx.x * 256 + tid;
    float acc = -INFINITY;
    if (v < V) {
        acc = g_logitp[v] + g_logitp[VP + v] + g_logitp[2 * VP + v] + g_logitp[3 * VP + v];
        out[v] = acc;
    }
    sred[tid] = acc;
    __syncthreads();
    for (int o = 128; o > 0; o >>= 1) {
        if (tid < o) sred[tid] = fmaxf(sred[tid], sred[tid + o]);
        __syncthreads();
    }
    float bm = sred[0];
    __syncthreads();
    sred[tid] = (v < V) ? expf(acc - bm) : 0.f;
    __syncthreads();
    for (int o = 128; o > 0; o >>= 1) {
        if (tid < o) sred[tid] += sred[tid + o];
        __syncthreads();
    }
    if (tid == 0) {
        g_mpart[blockIdx.x] = bm;
        g_spart[blockIdx.x] = sred[0];
    }
}

// ---------------- K11: fused lse + final subtract (197 blocks) ------------------
__global__ void k_lse_final(float* __restrict__ out) {
    __shared__ float sm_[256];
    __shared__ float ss[256];
    int t = threadIdx.x;
    float m = (t < 197) ? g_mpart[t] : -INFINITY;
    sm_[t] = m;
    __syncthreads();
    for (int o = 128; o > 0; o >>= 1) {
        if (t < o) sm_[t] = fmaxf(sm_[t], sm_[t + o]);
        __syncthreads();
    }
    float M = sm_[0];
    float s = (t < 197) ? g_spart[t] * expf(g_mpart[t] - M) : 0.f;
    ss[t] = s;
    __syncthreads();
    for (int o = 128; o > 0; o >>= 1) {
        if (t < o) ss[t] += ss[t + o];
        __syncthreads();
    }
    float lse = M + logf(ss[0]);
    int v = blockIdx.x * 256 + t;
    if (v < V) out[v] = out[v] - lse;
}

// ---------------- launcher ----------------
extern "C" void kernel_launch(void* const* d_in, const int* in_sizes, int n_in,
                              void* d_out, int out_size) {
    const int*   input  = (const int*)d_in[0];
    const float* hidden = (const float*)d_in[1];
    const float* enc    = (const float*)d_in[2];
    const float* emb    = (const float*)d_in[3];
    const float* Wq     = (const float*)d_in[4];
    const float* Wk     = (const float*)d_in[5];
    const float* wv     = (const float*)d_in[6];
    const float* W_ih0  = (const float*)d_in[7];
    const float* W_hh0  = (const float*)d_in[8];
    const float* b_ih0  = (const float*)d_in[9];
    const float* b_hh0  = (const float*)d_in[10];
    const float* W_ih1  = (const float*)d_in[11];
    const float* W_hh1  = (const float*)d_in[12];
    const float* b_ih1  = (const float*)d_in[13];
    const float* b_hh1  = (const float*)d_in[14];
    const float* Wd     = (const float*)d_in[15];
    const float* bd     = (const float*)d_in[16];

    float* out = (float*)d_out;  // [0,V) logp ; [V,V+H) h0n ; [V+H,V+2H) h1n

    static int smem_set = 0;
    if (!smem_set) {
        cudaFuncSetAttribute(k_attn_gemm, cudaFuncAttributeMaxDynamicSharedMemorySize,
                             GEMM_SMEM_BYTES);
        smem_set = 1;
    }

    k_prep<<<4736, 256>>>(enc, Wk, hidden, Wq);
    k_attn_gemm<<<dim3(8, 32), 256, GEMM_SMEM_BYTES>>>(wv);
    k_softmax<<<1, 1024>>>();
    k_ctx_partial<<<256, 256>>>();
    k_build_x<<<8, 256>>>(input, emb);
    k_gru_gemv0<<<768, 256>>>(W_ih0, W_hh0, b_ih0, b_hh0, hidden);
    k_gru_gemv1<<<768, 256>>>(W_ih1, W_hh1, b_ih1, b_hh1, hidden, out + V);
    k_logits_part<<<dim3(197, 4), 256>>>(Wd, bd, hidden, out + V + H);
    k_logits_comb<<<197, 256>>>(out);
    k_lse_final<<<197, 256>>>(out);
}

// round 15
// speedup vs baseline: 1.0396x; 1.0396x over previous
#include <cuda_runtime.h>
#include <cuda_bf16.h>
#include <math.h>
#include <stdint.h>

#define H 1024
#define L 4096
#define V 50257
#define G3 3072
#define X2 2048
#define NPART 8
#define VP 50432           // 197*256
#define CTXP 256           // ctx partial chunks

// ---------------- scratch (device globals, no allocation) ----------------
__device__ __nv_bfloat16 g_encb[L * H];   // bf16 enc, row-major [l][h]
__device__ uint32_t g_wkbT[H * (H / 2)];  // Wk bf16x2, TRANSPOSED: [n][k2]
__device__ float g_qwp[32 * H];           // qW partials
__device__ float g_scorep[NPART * L];     // [bn][l] partial scores
__device__ float g_attn[L];               // UNNORMALIZED exp(s)
__device__ float g_invS;                  // 1/sum(exp)
__device__ float g_ctxp[CTXP * H];        // context partials
__device__ float g_x[X2];                 // concat(context, relu(emb))
__device__ float g_gi0[G3], g_gh0[G3];    // GRU layer-0 gates
__device__ float g_gi1[G3], g_gh1[G3];    // GRU layer-1 gates
__device__ float g_logitp[4 * VP];        // split-K logits partials
__device__ float g_mpart[256];
__device__ float g_spart[256];

__device__ __forceinline__ float sigmoidf_(float x) { return 1.0f / (1.0f + expf(-x)); }

__device__ __forceinline__ uint32_t pk(float lo, float hi) {
    __nv_bfloat162 v = __floats2bfloat162_rn(lo, hi);
    return *(uint32_t*)&v;
}

__device__ __forceinline__ void mma_bf16(float c[4], const uint32_t a[4],
                                         uint32_t b0, uint32_t b1) {
    asm volatile(
        "mma.sync.aligned.m16n8k16.row.col.f32.bf16.bf16.f32 "
        "{%0,%1,%2,%3}, {%4,%5,%6,%7}, {%8,%9}, {%0,%1,%2,%3};"
        : "+f"(c[0]), "+f"(c[1]), "+f"(c[2]), "+f"(c[3])
        : "r"(a[0]), "r"(a[1]), "r"(a[2]), "r"(a[3]), "r"(b0), "r"(b1));
}

__device__ __forceinline__ void ldsm4(uint32_t& r0, uint32_t& r1, uint32_t& r2,
                                      uint32_t& r3, uint32_t addr) {
    asm volatile("ldmatrix.sync.aligned.m8n8.x4.shared.b16 {%0,%1,%2,%3}, [%4];"
                 : "=r"(r0), "=r"(r1), "=r"(r2), "=r"(r3) : "r"(addr));
}

__device__ __forceinline__ void cpa16(uint32_t dst, const void* src) {
    asm volatile("cp.async.cg.shared.global [%0], [%1], 16;\n"
                 :: "r"(dst), "l"(__cvta_generic_to_global(src)));
}

// ---------------- K0: fused prep (cvt_enc | cvt_wk | qw_partial) ---------------
__global__ void k_prep(const float* __restrict__ enc, const float* __restrict__ Wk,
                       const float* __restrict__ hidden, const float* __restrict__ Wq) {
    int b = blockIdx.x;
    int tid = threadIdx.x;
    if (b < 4096) {
        int idx = (b * 256 + tid) * 4;
        float4 v = *(const float4*)(enc + idx);
        uint2 o = make_uint2(pk(v.x, v.y), pk(v.z, v.w));
        *(uint2*)&g_encb[idx] = o;
    } else if (b < 4608) {
        int idx = (b - 4096) * 256 + tid;   // 0..131071
        int n = idx & 1023;
        int k2q = idx >> 10;
        uint4 o;
        const float* c = Wk + (size_t)(8 * k2q) * H + n;
        o.x = pk(c[0],     c[H]);
        o.y = pk(c[2 * H], c[3 * H]);
        o.z = pk(c[4 * H], c[5 * H]);
        o.w = pk(c[6 * H], c[7 * H]);
        *(uint4*)&g_wkbT[(size_t)n * 512 + k2q * 4] = o;
    } else {
        int r = b - 4608;                   // 0..127
        int j = (r & 3) * 256 + tid;
        int i0 = (r >> 2) * 32;
        const float* q = hidden + H;
        float acc = 0.f;
#pragma unroll
        for (int i = 0; i < 32; i++)
            acc += q[i0 + i] * Wq[(size_t)(i0 + i) * H + j];
        g_qwp[(r >> 2) * H + j] = acc;
    }
}

// ---------------- K3: attention GEMM (R13-proven: BK=32, 5-stage ring) ---------
// BM=128, BN=128; grid (8 bn, 32 bm); 8 warps = 2m x 4n; warp 64x32.
// smem BYTES: A stage s @ s*10240 (s=0..4) | B stage s @ 51200 + s*10240 |
//   sqw @102400 (512B) | swv @102912 (512B)  => total 103424
#define GEMM_SMEM_BYTES 103424
__global__ void __launch_bounds__(256, 2)
k_attn_gemm(const float* __restrict__ wv) {
    extern __shared__ uint32_t sm[];
    const int tid = threadIdx.x;
    const int warp = tid >> 5, lane = tid & 31;
    const int wm = warp & 1, wn = warp >> 1;     // 2 m x 4 n
    const int g = lane >> 2, t = lane & 3;
    const int bn = blockIdx.x, bm = blockIdx.y;

    float* sqw = (float*)((char*)sm + 102400);
    float* swv = (float*)((char*)sm + 102912);

    if (tid < 128) {
        int col = bn * 128 + tid;
        float s = 0.f;
#pragma unroll
        for (int p = 0; p < 32; p++) s += g_qwp[p * H + col];
        sqw[tid] = s;
        swv[tid] = wv[col];
    }

    float acc[4][4][4];
#pragma unroll
    for (int mt = 0; mt < 4; mt++)
#pragma unroll
        for (int nt = 0; nt < 4; nt++)
#pragma unroll
            for (int i = 0; i < 4; i++) acc[mt][nt][i] = 0.f;

    const int prow = tid >> 1, part = tid & 1;
    const __nv_bfloat16* Ag = g_encb + (size_t)(bm * 128 + prow) * H + part * 16;
    const uint32_t* Bg = g_wkbT + (size_t)(bn * 128 + prow) * 512 + part * 8;
    const uint32_t smBase = (uint32_t)__cvta_generic_to_shared(sm);
    const uint32_t aDst = smBase + (uint32_t)(prow * 20 + part * 8) * 4;
    const uint32_t bDst = smBase + 51200u + (uint32_t)(prow * 20 + part * 8) * 4;

#define LOAD_STAGE(it, st)                                               \
    {                                                                    \
        const uint32_t so = (uint32_t)(st) * 10240u;                     \
        const __nv_bfloat16* as_ = Ag + (size_t)(it) * 32;               \
        cpa16(aDst + so,      as_);                                      \
        cpa16(aDst + so + 16, as_ + 8);                                  \
        const uint32_t* bs_ = Bg + (size_t)(it) * 16;                    \
        cpa16(bDst + so,      bs_);                                      \
        cpa16(bDst + so + 16, bs_ + 4);                                  \
        asm volatile("cp.async.commit_group;");                          \
    }

    const uint32_t lrow = lane & 15, lcol = (lane >> 4) * 4;
    uint32_t aOff[4], bOff[2];
#pragma unroll
    for (int mt = 0; mt < 4; mt++)
        aOff[mt] = smBase + ((wm * 64 + mt * 16 + lrow) * 20 + lcol) * 4;
#pragma unroll
    for (int p = 0; p < 2; p++)
        bOff[p] = smBase + 51200u + ((wn * 32 + p * 16 + lrow) * 20 + lcol) * 4;

#define COMPUTE_STAGE(st)                                                \
    {                                                                    \
        const uint32_t so = (uint32_t)(st) * 10240u;                     \
        _Pragma("unroll")                                                \
        for (int ks = 0; ks < 2; ks++) {                                 \
            const uint32_t ko = so + (uint32_t)ks * 32u;                 \
            uint32_t a[4][4];                                            \
            _Pragma("unroll")                                            \
            for (int mt = 0; mt < 4; mt++)                               \
                ldsm4(a[mt][0], a[mt][1], a[mt][2], a[mt][3], aOff[mt] + ko); \
            _Pragma("unroll")                                            \
            for (int p = 0; p < 2; p++) {                                \
                uint32_t b0e, b0o, b1e, b1o;                             \
                ldsm4(b0e, b0o, b1e, b1o, bOff[p] + ko);                 \
                _Pragma("unroll")                                        \
                for (int mt = 0; mt < 4; mt++) {                         \
                    mma_bf16(acc[mt][2 * p],     a[mt], b0e, b1e);       \
                    mma_bf16(acc[mt][2 * p + 1], a[mt], b0o, b1o);       \
                }                                                        \
            }                                                            \
        }                                                                \
    }

    LOAD_STAGE(0, 0);
    LOAD_STAGE(1, 1);
    LOAD_STAGE(2, 2);
    LOAD_STAGE(3, 3);

    for (int base = 0; base < 25; base += 5) {
#pragma unroll
        for (int st = 0; st < 5; ++st) {
            const int it = base + st;
            asm volatile("cp.async.wait_group 3;");
            __syncthreads();
            LOAD_STAGE(it + 4, (st + 4) % 5);
            COMPUTE_STAGE(st);
        }
    }
    asm volatile("cp.async.wait_group 3;");
    __syncthreads();
    LOAD_STAGE(29, 4);
    COMPUTE_STAGE(0);
    asm volatile("cp.async.wait_group 3;");
    __syncthreads();
    LOAD_STAGE(30, 0);
    COMPUTE_STAGE(1);
    asm volatile("cp.async.wait_group 3;");
    __syncthreads();
    LOAD_STAGE(31, 1);
    COMPUTE_STAGE(2);
    asm volatile("cp.async.wait_group 3;");
    __syncthreads();
    COMPUTE_STAGE(3);
    asm volatile("cp.async.wait_group 2;");
    __syncthreads();
    COMPUTE_STAGE(4);
    asm volatile("cp.async.wait_group 1;");
    __syncthreads();
    COMPUTE_STAGE(0);
    asm volatile("cp.async.wait_group 0;");
    __syncthreads();
    COMPUTE_STAGE(1);

    float s[8];
#pragma unroll
    for (int i = 0; i < 8; i++) s[i] = 0.f;
#pragma unroll
    for (int mt = 0; mt < 4; mt++) {
#pragma unroll
        for (int nt = 0; nt < 4; nt++) {
            int lc = wn * 32 + nt * 8 + 2 * t;
            float qw0 = sqw[lc], qw1 = sqw[lc + 1];
            float w0 = swv[lc], w1 = swv[lc + 1];
            s[mt * 2 + 0] += tanhf(acc[mt][nt][0] + qw0) * w0 + tanhf(acc[mt][nt][1] + qw1) * w1;
            s[mt * 2 + 1] += tanhf(acc[mt][nt][2] + qw0) * w0 + tanhf(acc[mt][nt][3] + qw1) * w1;
        }
    }
#pragma unroll
    for (int i = 0; i < 8; i++) {
        s[i] += __shfl_xor_sync(0xffffffffu, s[i], 1);
        s[i] += __shfl_xor_sync(0xffffffffu, s[i], 2);
    }
    __syncthreads();
    float* red = (float*)sm;
    if (t == 0) {
#pragma unroll
        for (int mt = 0; mt < 4; mt++) {
            red[(wm * 64 + mt * 16 + g) * 4 + wn]     = s[2 * mt];
            red[(wm * 64 + mt * 16 + g + 8) * 4 + wn] = s[2 * mt + 1];
        }
    }
    __syncthreads();
    if (tid < 128) {
        float vsum = red[tid * 4] + red[tid * 4 + 1] + red[tid * 4 + 2] + red[tid * 4 + 3];
        g_scorep[(size_t)bn * L + bm * 128 + tid] = vsum;
    }
}

// ---------------- K4: softmax sum (max-free: |score| <= sum|wv| << 88) ----------
__global__ void k_softmax() {
    __shared__ float sred[32];
    int tid = threadIdx.x;
    int wid = tid >> 5, lane = tid & 31;
    float4 v = make_float4(0.f, 0.f, 0.f, 0.f);
#pragma unroll
    for (int p = 0; p < NPART; p++) {
        float4 sp = *(const float4*)&g_scorep[(size_t)p * L + tid * 4];
        v.x += sp.x; v.y += sp.y; v.z += sp.z; v.w += sp.w;
    }
    float4 e = make_float4(expf(v.x), expf(v.y), expf(v.z), expf(v.w));
    float s = e.x + e.y + e.z + e.w;
#pragma unroll
    for (int o = 16; o > 0; o >>= 1) s += __shfl_xor_sync(0xffffffffu, s, o);
    if (lane == 0) sred[wid] = s;
    __syncthreads();
    if (wid == 0) {
        float q = sred[lane];
#pragma unroll
        for (int o = 16; o > 0; o >>= 1) q += __shfl_xor_sync(0xffffffffu, q, o);
        if (lane == 0) g_invS = 1.0f / q;
    }
    *(float4*)&g_attn[tid * 4] = e;
}

// ---------------- K5: ctx partials, bf16x2 (grid 512, 256 thr, 16 l each) ------
__global__ void k_ctx_partial() {
    int jhalf = blockIdx.x & 1;
    int lc = blockIdx.x >> 1;                 // 0..255
    int j0 = jhalf * 512 + threadIdx.x * 2;
    int l0 = lc * 16;
    float a0 = 0.f, a1 = 0.f;
#pragma unroll
    for (int l = l0; l < l0 + 16; l++) {
        float a = g_attn[l];
        __nv_bfloat162 w = *(const __nv_bfloat162*)&g_encb[(size_t)l * H + j0];
        float2 f = __bfloat1622float2(w);
        a0 += a * f.x;
        a1 += a * f.y;
    }
    g_ctxp[lc * H + j0]     = a0;
    g_ctxp[lc * H + j0 + 1] = a1;
}

// ---------------- K6: x = concat(invS * ctx, relu(emb[token])) -----------------
__global__ void k_build_x(const int* __restrict__ input, const float* __restrict__ emb) {
    int idx = blockIdx.x * 256 + threadIdx.x;
    if (idx < H) {
        float s = 0.f;
#pragma unroll 16
        for (int p = 0; p < CTXP; p++) s += g_ctxp[p * H + idx];
        g_x[idx] = s * g_invS;
    } else {
        int tok = input[0];
        float e = emb[(size_t)tok * H + (idx - H)];
        g_x[idx] = fmaxf(e, 0.f);
    }
}

// ---------------- K7: GRU layer-0 GEMV ----------------
__global__ void k_gru_gemv0(const float* __restrict__ Wi, const float* __restrict__ Wh,
                            const float* __restrict__ bi, const float* __restrict__ bh,
                            const float* __restrict__ hidden) {
    __shared__ float sxh[X2 + H];
    int tid = threadIdx.x;
    for (int i = tid; i < X2; i += 256) sxh[i] = g_x[i];
    for (int i = tid; i < H; i += 256) sxh[X2 + i] = hidden[i];
    __syncthreads();

    int warp = blockIdx.x * 8 + (tid >> 5);
    int lane = tid & 31;
    if (warp < G3) {
        const float* W = Wi + (size_t)warp * X2;
        float acc = 0.f;
#pragma unroll
        for (int c0 = 0; c0 < X2; c0 += 128) {
            int c = c0 + lane * 4;
            float4 w = *(const float4*)(W + c);
            acc += w.x * sxh[c] + w.y * sxh[c + 1] + w.z * sxh[c + 2] + w.w * sxh[c + 3];
        }
#pragma unroll
        for (int o = 16; o > 0; o >>= 1) acc += __shfl_down_sync(0xffffffffu, acc, o);
        if (lane == 0) g_gi0[warp] = acc + bi[warp];
    } else {
        int r = warp - G3;
        const float* W = Wh + (size_t)r * H;
        float acc = 0.f;
#pragma unroll
        for (int c0 = 0; c0 < H; c0 += 128) {
            int c = c0 + lane * 4;
            float4 w = *(const float4*)(W + c);
            acc += w.x * sxh[X2 + c] + w.y * sxh[X2 + c + 1] + w.z * sxh[X2 + c + 2] + w.w * sxh[X2 + c + 3];
        }
#pragma unroll
        for (int o = 16; o > 0; o >>= 1) acc += __shfl_down_sync(0xffffffffu, acc, o);
        if (lane == 0) g_gh0[r] = acc + bh[r];
    }
}

// ---------------- K8: GRU layer-1 GEMV, fused layer-0 combine -------------------
__global__ void k_gru_gemv1(const float* __restrict__ Wi, const float* __restrict__ Wh,
                            const float* __restrict__ bi, const float* __restrict__ bh,
                            const float* __restrict__ hidden, float* __restrict__ out_h0) {
    __shared__ float sxh[2 * H];
    int tid = threadIdx.x;
    for (int i = tid; i < H; i += 256) {
        float r = sigmoidf_(g_gi0[i] + g_gh0[i]);
        float z = sigmoidf_(g_gi0[i + H] + g_gh0[i + H]);
        float n = tanhf(g_gi0[i + 2 * H] + r * g_gh0[i + 2 * H]);
        float hn = (1.0f - z) * n + z * hidden[i];
        sxh[i] = hn;
        if (blockIdx.x == 0) out_h0[i] = hn;
        sxh[H + i] = hidden[H + i];
    }
    __syncthreads();

    int warp = blockIdx.x * 8 + (tid >> 5);
    int lane = tid & 31;
    const float* W = (warp < G3) ? (Wi + (size_t)warp * H)
                                 : (Wh + (size_t)(warp - G3) * H);
    const float* xv = (warp < G3) ? sxh : (sxh + H);
    float acc = 0.f;
#pragma unroll
    for (int c0 = 0; c0 < H; c0 += 128) {
        int c = c0 + lane * 4;
        float4 w = *(const float4*)(W + c);
        acc += w.x * xv[c] + w.y * xv[c + 1] + w.z * xv[c + 2] + w.w * xv[c + 3];
    }
#pragma unroll
    for (int o = 16; o > 0; o >>= 1) acc += __shfl_down_sync(0xffffffffu, acc, o);
    if (lane == 0) {
        if (warp < G3) g_gi1[warp] = acc + bi[warp];
        else           g_gh1[warp - G3] = acc + bh[warp - G3];
    }
}

// ---------------- K9: split-K logits partials (grid 197 x 4) -------------------
__global__ void k_logits_part(const float* __restrict__ Wd, const float* __restrict__ bd,
                              const float* __restrict__ hidden, float* __restrict__ out_h1) {
    __shared__ float sh[256];
    int tid = threadIdx.x;
    int kp = blockIdx.y;
    int i = kp * 256 + tid;
    {
        float r = sigmoidf_(g_gi1[i] + g_gh1[i]);
        float z = sigmoidf_(g_gi1[i + H] + g_gh1[i + H]);
        float n = tanhf(g_gi1[i + 2 * H] + r * g_gh1[i + 2 * H]);
        float hn = (1.0f - z) * n + z * hidden[H + i];
        sh[tid] = hn;
        if (blockIdx.x == 0) out_h1[i] = hn;
    }
    __syncthreads();

    int v = blockIdx.x * 256 + tid;
    if (v < V) {
        float acc = (kp == 0) ? bd[v] : 0.f;
        const float* Wb = Wd + (size_t)(kp * 256) * V + v;
#pragma unroll 16
        for (int h = 0; h < 256; h++)
            acc += sh[h] * Wb[(size_t)h * V];
        g_logitp[kp * VP + v] = acc;
    }
}

// ---------------- K10: combine partials + softmax stats ------------------------
__global__ void k_logits_comb(float* __restrict__ out) {
    __shared__ float sred[256];
    int tid = threadIdx.x;
    int v = blockIdx.x * 256 + tid;
    float acc = -INFINITY;
    if (v < V) {
        acc = g_logitp[v] + g_logitp[VP + v] + g_logitp[2 * VP + v] + g_logitp[3 * VP + v];
        out[v] = acc;
    }
    sred[tid] = acc;
    __syncthreads();
    for (int o = 128; o > 0; o >>= 1) {
        if (tid < o) sred[tid] = fmaxf(sred[tid], sred[tid + o]);
        __syncthreads();
    }
    float bm = sred[0];
    __syncthreads();
    sred[tid] = (v < V) ? expf(acc - bm) : 0.f;
    __syncthreads();
    for (int o = 128; o > 0; o >>= 1) {
        if (tid < o) sred[tid] += sred[tid + o];
        __syncthreads();
    }
    if (tid == 0) {
        g_mpart[blockIdx.x] = bm;
        g_spart[blockIdx.x] = sred[0];
    }
}

// ---------------- K11: fused lse + final subtract (197 blocks) ------------------
__global__ void k_lse_final(float* __restrict__ out) {
    __shared__ float sm_[256];
    __shared__ float ss[256];
    int t = threadIdx.x;
    float m = (t < 197) ? g_mpart[t] : -INFINITY;
    sm_[t] = m;
    __syncthreads();
    for (int o = 128; o > 0; o >>= 1) {
        if (t < o) sm_[t] = fmaxf(sm_[t], sm_[t + o]);
        __syncthreads();
    }
    float M = sm_[0];
    float s = (t < 197) ? g_spart[t] * expf(g_mpart[t] - M) : 0.f;
    ss[t] = s;
    __syncthreads();
    for (int o = 128; o > 0; o >>= 1) {
        if (t < o) ss[t] += ss[t + o];
        __syncthreads();
    }
    float lse = M + logf(ss[0]);
    int v = blockIdx.x * 256 + t;
    if (v < V) out[v] = out[v] - lse;
}

// ---------------- launcher ----------------
extern "C" void kernel_launch(void* const* d_in, const int* in_sizes, int n_in,
                              void* d_out, int out_size) {
    const int*   input  = (const int*)d_in[0];
    const float* hidden = (const float*)d_in[1];
    const float* enc    = (const float*)d_in[2];
    const float* emb    = (const float*)d_in[3];
    const float* Wq     = (const float*)d_in[4];
    const float* Wk     = (const float*)d_in[5];
    const float* wv     = (const float*)d_in[6];
    const float* W_ih0  = (const float*)d_in[7];
    const float* W_hh0  = (const float*)d_in[8];
    const float* b_ih0  = (const float*)d_in[9];
    const float* b_hh0  = (const float*)d_in[10];
    const float* W_ih1  = (const float*)d_in[11];
    const float* W_hh1  = (const float*)d_in[12];
    const float* b_ih1  = (const float*)d_in[13];
    const float* b_hh1  = (const float*)d_in[14];
    const float* Wd     = (const float*)d_in[15];
    const float* bd     = (const float*)d_in[16];

    float* out = (float*)d_out;  // [0,V) logp ; [V,V+H) h0n ; [V+H,V+2H) h1n

    static int smem_set = 0;
    if (!smem_set) {
        cudaFuncSetAttribute(k_attn_gemm, cudaFuncAttributeMaxDynamicSharedMemorySize,
                             GEMM_SMEM_BYTES);
        smem_set = 1;
    }

    k_prep<<<4736, 256>>>(enc, Wk, hidden, Wq);
    k_attn_gemm<<<dim3(8, 32), 256, GEMM_SMEM_BYTES>>>(wv);
    k_softmax<<<1, 1024>>>();
    k_ctx_partial<<<512, 256>>>();
    k_build_x<<<8, 256>>>(input, emb);
    k_gru_gemv0<<<768, 256>>>(W_ih0, W_hh0, b_ih0, b_hh0, hidden);
    k_gru_gemv1<<<768, 256>>>(W_ih1, W_hh1, b_ih1, b_hh1, hidden, out + V);
    k_logits_part<<<dim3(197, 4), 256>>>(Wd, bd, hidden, out + V + H);
    k_logits_comb<<<197, 256>>>(out);
    k_lse_final<<<197, 256>>>(out);
}

// round 16
// speedup vs baseline: 1.0732x; 1.0323x over previous
#include <cuda_runtime.h>
#include <cuda_bf16.h>
#include <math.h>
#include <stdint.h>

#define H 1024
#define L 4096
#define V 50257
#define G3 3072
#define X2 2048
#define NPART 8
#define VP 50432           // 197*256
#define CTXP 128           // ctx partial chunks (32 l each)

// ---------------- scratch (device globals, no allocation) ----------------
__device__ __nv_bfloat16 g_encb[L * H];   // bf16 enc, row-major [l][h]
__device__ uint32_t g_wkbT[H * (H / 2)];  // Wk bf16x2, TRANSPOSED: [n][k2]
__device__ float g_qwp[32 * H];           // qW partials
__device__ float g_scorep[NPART * L];     // [bn][l] partial scores
__device__ float g_espart[CTXP];          // per-chunk sums of exp(score)
__device__ float g_ctxp[CTXP * H];        // context partials (unnormalized)
__device__ float g_x[X2];                 // concat(context, relu(emb))
__device__ float g_gi0[G3], g_gh0[G3];    // GRU layer-0 gates
__device__ float g_gi1[G3], g_gh1[G3];    // GRU layer-1 gates
__device__ float g_logitp[4 * VP];        // split-K logits partials
__device__ float g_mpart[256];
__device__ float g_spart[256];

__device__ __forceinline__ float sigmoidf_(float x) { return 1.0f / (1.0f + expf(-x)); }

__device__ __forceinline__ uint32_t pk(float lo, float hi) {
    __nv_bfloat162 v = __floats2bfloat162_rn(lo, hi);
    return *(uint32_t*)&v;
}

__device__ __forceinline__ void mma_bf16(float c[4], const uint32_t a[4],
                                         uint32_t b0, uint32_t b1) {
    asm volatile(
        "mma.sync.aligned.m16n8k16.row.col.f32.bf16.bf16.f32 "
        "{%0,%1,%2,%3}, {%4,%5,%6,%7}, {%8,%9}, {%0,%1,%2,%3};"
        : "+f"(c[0]), "+f"(c[1]), "+f"(c[2]), "+f"(c[3])
        : "r"(a[0]), "r"(a[1]), "r"(a[2]), "r"(a[3]), "r"(b0), "r"(b1));
}

__device__ __forceinline__ void ldsm4(uint32_t& r0, uint32_t& r1, uint32_t& r2,
                                      uint32_t& r3, uint32_t addr) {
    asm volatile("ldmatrix.sync.aligned.m8n8.x4.shared.b16 {%0,%1,%2,%3}, [%4];"
                 : "=r"(r0), "=r"(r1), "=r"(r2), "=r"(r3) : "r"(addr));
}

__device__ __forceinline__ void cpa16(uint32_t dst, const void* src) {
    asm volatile("cp.async.cg.shared.global [%0], [%1], 16;\n"
                 :: "r"(dst), "l"(__cvta_generic_to_global(src)));
}

// ---------------- K0: fused prep (cvt_enc | cvt_wk | qw_partial) ---------------
__global__ void k_prep(const float* __restrict__ enc, const float* __restrict__ Wk,
                       const float* __restrict__ hidden, const float* __restrict__ Wq) {
    int b = blockIdx.x;
    int tid = threadIdx.x;
    if (b < 4096) {
        int idx = (b * 256 + tid) * 4;
        float4 v = *(const float4*)(enc + idx);
        uint2 o = make_uint2(pk(v.x, v.y), pk(v.z, v.w));
        *(uint2*)&g_encb[idx] = o;
    } else if (b < 4608) {
        int idx = (b - 4096) * 256 + tid;   // 0..131071
        int n = idx & 1023;
        int k2q = idx >> 10;
        uint4 o;
        const float* c = Wk + (size_t)(8 * k2q) * H + n;
        o.x = pk(c[0],     c[H]);
        o.y = pk(c[2 * H], c[3 * H]);
        o.z = pk(c[4 * H], c[5 * H]);
        o.w = pk(c[6 * H], c[7 * H]);
        *(uint4*)&g_wkbT[(size_t)n * 512 + k2q * 4] = o;
    } else {
        int r = b - 4608;                   // 0..127
        int j = (r & 3) * 256 + tid;
        int i0 = (r >> 2) * 32;
        const float* q = hidden + H;
        float acc = 0.f;
#pragma unroll
        for (int i = 0; i < 32; i++)
            acc += q[i0 + i] * Wq[(size_t)(i0 + i) * H + j];
        g_qwp[(r >> 2) * H + j] = acc;
    }
}

// ---------------- K3: attention GEMM (R13-proven: BK=32, 5-stage ring) ---------
// BM=128, BN=128; grid (8 bn, 32 bm); 8 warps = 2m x 4n; warp 64x32.
// smem BYTES: A stage s @ s*10240 (s=0..4) | B stage s @ 51200 + s*10240 |
//   sqw @102400 (512B) | swv @102912 (512B)  => total 103424
#define GEMM_SMEM_BYTES 103424
__global__ void __launch_bounds__(256, 2)
k_attn_gemm(const float* __restrict__ wv) {
    extern __shared__ uint32_t sm[];
    const int tid = threadIdx.x;
    const int warp = tid >> 5, lane = tid & 31;
    const int wm = warp & 1, wn = warp >> 1;     // 2 m x 4 n
    const int g = lane >> 2, t = lane & 3;
    const int bn = blockIdx.x, bm = blockIdx.y;

    float* sqw = (float*)((char*)sm + 102400);
    float* swv = (float*)((char*)sm + 102912);

    if (tid < 128) {
        int col = bn * 128 + tid;
        float s = 0.f;
#pragma unroll
        for (int p = 0; p < 32; p++) s += g_qwp[p * H + col];
        sqw[tid] = s;
        swv[tid] = wv[col];
    }

    float acc[4][4][4];
#pragma unroll
    for (int mt = 0; mt < 4; mt++)
#pragma unroll
        for (int nt = 0; nt < 4; nt++)
#pragma unroll
            for (int i = 0; i < 4; i++) acc[mt][nt][i] = 0.f;

    const int prow = tid >> 1, part = tid & 1;
    const __nv_bfloat16* Ag = g_encb + (size_t)(bm * 128 + prow) * H + part * 16;
    const uint32_t* Bg = g_wkbT + (size_t)(bn * 128 + prow) * 512 + part * 8;
    const uint32_t smBase = (uint32_t)__cvta_generic_to_shared(sm);
    const uint32_t aDst = smBase + (uint32_t)(prow * 20 + part * 8) * 4;
    const uint32_t bDst = smBase + 51200u + (uint32_t)(prow * 20 + part * 8) * 4;

#define LOAD_STAGE(it, st)                                               \
    {                                                                    \
        const uint32_t so = (uint32_t)(st) * 10240u;                     \
        const __nv_bfloat16* as_ = Ag + (size_t)(it) * 32;               \
        cpa16(aDst + so,      as_);                                      \
        cpa16(aDst + so + 16, as_ + 8);                                  \
        const uint32_t* bs_ = Bg + (size_t)(it) * 16;                    \
        cpa16(bDst + so,      bs_);                                      \
        cpa16(bDst + so + 16, bs_ + 4);                                  \
        asm volatile("cp.async.commit_group;");                          \
    }

    const uint32_t lrow = lane & 15, lcol = (lane >> 4) * 4;
    uint32_t aOff[4], bOff[2];
#pragma unroll
    for (int mt = 0; mt < 4; mt++)
        aOff[mt] = smBase + ((wm * 64 + mt * 16 + lrow) * 20 + lcol) * 4;
#pragma unroll
    for (int p = 0; p < 2; p++)
        bOff[p] = smBase + 51200u + ((wn * 32 + p * 16 + lrow) * 20 + lcol) * 4;

#define COMPUTE_STAGE(st)                                                \
    {                                                                    \
        const uint32_t so = (uint32_t)(st) * 10240u;                     \
        _Pragma("unroll")                                                \
        for (int ks = 0; ks < 2; ks++) {                                 \
            const uint32_t ko = so + (uint32_t)ks * 32u;                 \
            uint32_t a[4][4];                                            \
            _Pragma("unroll")                                            \
            for (int mt = 0; mt < 4; mt++)                               \
                ldsm4(a[mt][0], a[mt][1], a[mt][2], a[mt][3], aOff[mt] + ko); \
            _Pragma("unroll")                                            \
            for (int p = 0; p < 2; p++) {                                \
                uint32_t b0e, b0o, b1e, b1o;                             \
                ldsm4(b0e, b0o, b1e, b1o, bOff[p] + ko);                 \
                _Pragma("unroll")                                        \
                for (int mt = 0; mt < 4; mt++) {                         \
                    mma_bf16(acc[mt][2 * p],     a[mt], b0e, b1e);       \
                    mma_bf16(acc[mt][2 * p + 1], a[mt], b0o, b1o);       \
                }                                                        \
            }                                                            \
        }                                                                \
    }

    LOAD_STAGE(0, 0);
    LOAD_STAGE(1, 1);
    LOAD_STAGE(2, 2);
    LOAD_STAGE(3, 3);

    for (int base = 0; base < 25; base += 5) {
#pragma unroll
        for (int st = 0; st < 5; ++st) {
            const int it = base + st;
            asm volatile("cp.async.wait_group 3;");
            __syncthreads();
            LOAD_STAGE(it + 4, (st + 4) % 5);
            COMPUTE_STAGE(st);
        }
    }
    asm volatile("cp.async.wait_group 3;");
    __syncthreads();
    LOAD_STAGE(29, 4);
    COMPUTE_STAGE(0);
    asm volatile("cp.async.wait_group 3;");
    __syncthreads();
    LOAD_STAGE(30, 0);
    COMPUTE_STAGE(1);
    asm volatile("cp.async.wait_group 3;");
    __syncthreads();
    LOAD_STAGE(31, 1);
    COMPUTE_STAGE(2);
    asm volatile("cp.async.wait_group 3;");
    __syncthreads();
    COMPUTE_STAGE(3);
    asm volatile("cp.async.wait_group 2;");
    __syncthreads();
    COMPUTE_STAGE(4);
    asm volatile("cp.async.wait_group 1;");
    __syncthreads();
    COMPUTE_STAGE(0);
    asm volatile("cp.async.wait_group 0;");
    __syncthreads();
    COMPUTE_STAGE(1);

    float s[8];
#pragma unroll
    for (int i = 0; i < 8; i++) s[i] = 0.f;
#pragma unroll
    for (int mt = 0; mt < 4; mt++) {
#pragma unroll
        for (int nt = 0; nt < 4; nt++) {
            int lc = wn * 32 + nt * 8 + 2 * t;
            float qw0 = sqw[lc], qw1 = sqw[lc + 1];
            float w0 = swv[lc], w1 = swv[lc + 1];
            s[mt * 2 + 0] += tanhf(acc[mt][nt][0] + qw0) * w0 + tanhf(acc[mt][nt][1] + qw1) * w1;
            s[mt * 2 + 1] += tanhf(acc[mt][nt][2] + qw0) * w0 + tanhf(acc[mt][nt][3] + qw1) * w1;
        }
    }
#pragma unroll
    for (int i = 0; i < 8; i++) {
        s[i] += __shfl_xor_sync(0xffffffffu, s[i], 1);
        s[i] += __shfl_xor_sync(0xffffffffu, s[i], 2);
    }
    __syncthreads();
    float* red = (float*)sm;
    if (t == 0) {
#pragma unroll
        for (int mt = 0; mt < 4; mt++) {
            red[(wm * 64 + mt * 16 + g) * 4 + wn]     = s[2 * mt];
            red[(wm * 64 + mt * 16 + g + 8) * 4 + wn] = s[2 * mt + 1];
        }
    }
    __syncthreads();
    if (tid < 128) {
        float vsum = red[tid * 4] + red[tid * 4 + 1] + red[tid * 4 + 2] + red[tid * 4 + 3];
        g_scorep[(size_t)bn * L + bm * 128 + tid] = vsum;
    }
}

// ---------------- K5: ctx partials + FUSED softmax (grid 256, 256 thr) ---------
// block = (lc 0..127, jhalf 0..1); 32 l per chunk. Warp 0 computes e=exp(score)
// (max-free: |score| <= sum|wv| << 88) into smem; jhalf==0 emits chunk sum.
__global__ void k_ctx_partial() {
    __shared__ float se[32];
    int tid = threadIdx.x;
    int jhalf = blockIdx.x & 1;
    int lc = blockIdx.x >> 1;                 // 0..127
    int l0 = lc * 32;

    if (tid < 32) {
        float sc = 0.f;
#pragma unroll
        for (int p = 0; p < NPART; p++) sc += g_scorep[(size_t)p * L + l0 + tid];
        float e = expf(sc);
        se[tid] = e;
        float q = e;
#pragma unroll
        for (int o = 16; o > 0; o >>= 1) q += __shfl_xor_sync(0xffffffffu, q, o);
        if (tid == 0 && jhalf == 0) g_espart[lc] = q;
    }
    __syncthreads();

    int j0 = jhalf * 512 + tid * 2;
    float a0 = 0.f, a1 = 0.f;
#pragma unroll
    for (int l = 0; l < 32; l++) {
        float a = se[l];
        __nv_bfloat162 w = *(const __nv_bfloat162*)&g_encb[(size_t)(l0 + l) * H + j0];
        float2 f = __bfloat1622float2(w);
        a0 += a * f.x;
        a1 += a * f.y;
    }
    g_ctxp[lc * H + j0]     = a0;
    g_ctxp[lc * H + j0 + 1] = a1;
}

// ---------------- K6: x = concat(invS * ctx, relu(emb[token])) -----------------
__global__ void k_build_x(const int* __restrict__ input, const float* __restrict__ emb) {
    int idx = blockIdx.x * 256 + threadIdx.x;
    if (idx < H) {
        float S = 0.f;
#pragma unroll
        for (int p = 0; p < CTXP; p++) S += g_espart[p];
        float s = 0.f;
#pragma unroll
        for (int p = 0; p < CTXP; p++) s += g_ctxp[p * H + idx];
        g_x[idx] = s / S;
    } else {
        int tok = input[0];
        float e = emb[(size_t)tok * H + (idx - H)];
        g_x[idx] = fmaxf(e, 0.f);
    }
}

// ---------------- K7: GRU layer-0 GEMV ----------------
__global__ void k_gru_gemv0(const float* __restrict__ Wi, const float* __restrict__ Wh,
                            const float* __restrict__ bi, const float* __restrict__ bh,
                            const float* __restrict__ hidden) {
    __shared__ float sxh[X2 + H];
    int tid = threadIdx.x;
    for (int i = tid; i < X2; i += 256) sxh[i] = g_x[i];
    for (int i = tid; i < H; i += 256) sxh[X2 + i] = hidden[i];
    __syncthreads();

    int warp = blockIdx.x * 8 + (tid >> 5);
    int lane = tid & 31;
    if (warp < G3) {
        const float* W = Wi + (size_t)warp * X2;
        float acc = 0.f;
#pragma unroll
        for (int c0 = 0; c0 < X2; c0 += 128) {
            int c = c0 + lane * 4;
            float4 w = *(const float4*)(W + c);
            acc += w.x * sxh[c] + w.y * sxh[c + 1] + w.z * sxh[c + 2] + w.w * sxh[c + 3];
        }
#pragma unroll
        for (int o = 16; o > 0; o >>= 1) acc += __shfl_down_sync(0xffffffffu, acc, o);
        if (lane == 0) g_gi0[warp] = acc + bi[warp];
    } else {
        int r = warp - G3;
        const float* W = Wh + (size_t)r * H;
        float acc = 0.f;
#pragma unroll
        for (int c0 = 0; c0 < H; c0 += 128) {
            int c = c0 + lane * 4;
            float4 w = *(const float4*)(W + c);
            acc += w.x * sxh[X2 + c] + w.y * sxh[X2 + c + 1] + w.z * sxh[X2 + c + 2] + w.w * sxh[X2 + c + 3];
        }
#pragma unroll
        for (int o = 16; o > 0; o >>= 1) acc += __shfl_down_sync(0xffffffffu, acc, o);
        if (lane == 0) g_gh0[r] = acc + bh[r];
    }
}

// ---------------- K8: GRU layer-1 GEMV, fused layer-0 combine -------------------
__global__ void k_gru_gemv1(const float* __restrict__ Wi, const float* __restrict__ Wh,
                            const float* __restrict__ bi, const float* __restrict__ bh,
                            const float* __restrict__ hidden, float* __restrict__ out_h0) {
    __shared__ float sxh[2 * H];
    int tid = threadIdx.x;
    for (int i = tid; i < H; i += 256) {
        float r = sigmoidf_(g_gi0[i] + g_gh0[i]);
        float z = sigmoidf_(g_gi0[i + H] + g_gh0[i + H]);
        float n = tanhf(g_gi0[i + 2 * H] + r * g_gh0[i + 2 * H]);
        float hn = (1.0f - z) * n + z * hidden[i];
        sxh[i] = hn;
        if (blockIdx.x == 0) out_h0[i] = hn;
        sxh[H + i] = hidden[H + i];
    }
    __syncthreads();

    int warp = blockIdx.x * 8 + (tid >> 5);
    int lane = tid & 31;
    const float* W = (warp < G3) ? (Wi + (size_t)warp * H)
                                 : (Wh + (size_t)(warp - G3) * H);
    const float* xv = (warp < G3) ? sxh : (sxh + H);
    float acc = 0.f;
#pragma unroll
    for (int c0 = 0; c0 < H; c0 += 128) {
        int c = c0 + lane * 4;
        float4 w = *(const float4*)(W + c);
        acc += w.x * xv[c] + w.y * xv[c + 1] + w.z * xv[c + 2] + w.w * xv[c + 3];
    }
#pragma unroll
    for (int o = 16; o > 0; o >>= 1) acc += __shfl_down_sync(0xffffffffu, acc, o);
    if (lane == 0) {
        if (warp < G3) g_gi1[warp] = acc + bi[warp];
        else           g_gh1[warp - G3] = acc + bh[warp - G3];
    }
}

// ---------------- K9: split-K logits partials (grid 197 x 4) -------------------
__global__ void k_logits_part(const float* __restrict__ Wd, const float* __restrict__ bd,
                              const float* __restrict__ hidden, float* __restrict__ out_h1) {
    __shared__ float sh[256];
    int tid = threadIdx.x;
    int kp = blockIdx.y;
    int i = kp * 256 + tid;
    {
        float r = sigmoidf_(g_gi1[i] + g_gh1[i]);
        float z = sigmoidf_(g_gi1[i + H] + g_gh1[i + H]);
        float n = tanhf(g_gi1[i + 2 * H] + r * g_gh1[i + 2 * H]);
        float hn = (1.0f - z) * n + z * hidden[H + i];
        sh[tid] = hn;
        if (blockIdx.x == 0) out_h1[i] = hn;
    }
    __syncthreads();

    int v = blockIdx.x * 256 + tid;
    if (v < V) {
        float acc = (kp == 0) ? bd[v] : 0.f;
        const float* Wb = Wd + (size_t)(kp * 256) * V + v;
#pragma unroll 16
        for (int h = 0; h < 256; h++)
            acc += sh[h] * Wb[(size_t)h * V];
        g_logitp[kp * VP + v] = acc;
    }
}

// ---------------- K10: combine partials + softmax stats ------------------------
__global__ void k_logits_comb(float* __restrict__ out) {
    __shared__ float sred[256];
    int tid = threadIdx.x;
    int v = blockIdx.x * 256 + tid;
    float acc = -INFINITY;
    if (v < V) {
        acc = g_logitp[v] + g_logitp[VP + v] + g_logitp[2 * VP + v] + g_logitp[3 * VP + v];
        out[v] = acc;
    }
    sred[tid] = acc;
    __syncthreads();
    for (int o = 128; o > 0; o >>= 1) {
        if (tid < o) sred[tid] = fmaxf(sred[tid], sred[tid + o]);
        __syncthreads();
    }
    float bm = sred[0];
    __syncthreads();
    sred[tid] = (v < V) ? expf(acc - bm) : 0.f;
    __syncthreads();
    for (int o = 128; o > 0; o >>= 1) {
        if (tid < o) sred[tid] += sred[tid + o];
        __syncthreads();
    }
    if (tid == 0) {
        g_mpart[blockIdx.x] = bm;
        g_spart[blockIdx.x] = sred[0];
    }
}

// ---------------- K11: fused lse + final subtract (197 blocks) ------------------
__global__ void k_lse_final(float* __restrict__ out) {
    __shared__ float sm_[256];
    __shared__ float ss[256];
    int t = threadIdx.x;
    float m = (t < 197) ? g_mpart[t] : -INFINITY;
    sm_[t] = m;
    __syncthreads();
    for (int o = 128; o > 0; o >>= 1) {
        if (t < o) sm_[t] = fmaxf(sm_[t], sm_[t + o]);
        __syncthreads();
    }
    float M = sm_[0];
    float s = (t < 197) ? g_spart[t] * expf(g_mpart[t] - M) : 0.f;
    ss[t] = s;
    __syncthreads();
    for (int o = 128; o > 0; o >>= 1) {
        if (t < o) ss[t] += ss[t + o];
        __syncthreads();
    }
    float lse = M + logf(ss[0]);
    int v = blockIdx.x * 256 + t;
    if (v < V) out[v] = out[v] - lse;
}

// ---------------- launcher ----------------
extern "C" void kernel_launch(void* const* d_in, const int* in_sizes, int n_in,
                              void* d_out, int out_size) {
    const int*   input  = (const int*)d_in[0];
    const float* hidden = (const float*)d_in[1];
    const float* enc    = (const float*)d_in[2];
    const float* emb    = (const float*)d_in[3];
    const float* Wq     = (const float*)d_in[4];
    const float* Wk     = (const float*)d_in[5];
    const float* wv     = (const float*)d_in[6];
    const float* W_ih0  = (const float*)d_in[7];
    const float* W_hh0  = (const float*)d_in[8];
    const float* b_ih0  = (const float*)d_in[9];
    const float* b_hh0  = (const float*)d_in[10];
    const float* W_ih1  = (const float*)d_in[11];
    const float* W_hh1  = (const float*)d_in[12];
    const float* b_ih1  = (const float*)d_in[13];
    const float* b_hh1  = (const float*)d_in[14];
    const float* Wd     = (const float*)d_in[15];
    const float* bd     = (const float*)d_in[16];

    float* out = (float*)d_out;  // [0,V) logp ; [V,V+H) h0n ; [V+H,V+2H) h1n

    static int smem_set = 0;
    if (!smem_set) {
        cudaFuncSetAttribute(k_attn_gemm, cudaFuncAttributeMaxDynamicSharedMemorySize,
                             GEMM_SMEM_BYTES);
        smem_set = 1;
    }

    k_prep<<<4736, 256>>>(enc, Wk, hidden, Wq);
    k_attn_gemm<<<dim3(8, 32), 256, GEMM_SMEM_BYTES>>>(wv);
    k_ctx_partial<<<256, 256>>>();
    k_build_x<<<8, 256>>>(input, emb);
    k_gru_gemv0<<<768, 256>>>(W_ih0, W_hh0, b_ih0, b_hh0, hidden);
    k_gru_gemv1<<<768, 256>>>(W_ih1, W_hh1, b_ih1, b_hh1, hidden, out + V);
    k_logits_part<<<dim3(197, 4), 256>>>(Wd, bd, hidden, out + V + H);
    k_logits_comb<<<197, 256>>>(out);
    k_lse_final<<<197, 256>>>(out);
}

// round 17
// speedup vs baseline: 1.0926x; 1.0181x over previous
#include <cuda_runtime.h>
#include <cuda_bf16.h>
#include <math.h>
#include <stdint.h>

#define H 1024
#define L 4096
#define V 50257
#define G3 3072
#define X2 2048
#define NPART 8
#define VP 50432           // 197*256
#define CTXP 128           // ctx partial chunks (32 l each)

// ---------------- scratch (device globals, no allocation) ----------------
__device__ __nv_bfloat16 g_encb[L * H];   // bf16 enc, row-major [l][h]
__device__ uint32_t g_wkbT[H * (H / 2)];  // Wk bf16x2, TRANSPOSED: [n][k2]
__device__ float g_qwp[32 * H];           // qW partials
__device__ float g_scorep[NPART * L];     // [bn][l] partial scores
__device__ float g_espart[CTXP];          // per-chunk sums of exp(score)
__device__ float g_ctxp[CTXP * H];        // context partials (unnormalized)
__device__ float g_x[X2];                 // concat(context, relu(emb))
__device__ float g_gi0[G3], g_gh0[G3];    // GRU layer-0 gates
__device__ float g_gi1[G3], g_gh1[G3];    // GRU layer-1 gates
__device__ float g_logitp[4 * VP];        // split-K logits partials
__device__ float g_mpart[256];
__device__ float g_spart[256];

__device__ __forceinline__ float sigmoidf_(float x) { return 1.0f / (1.0f + expf(-x)); }

__device__ __forceinline__ uint32_t pk(float lo, float hi) {
    __nv_bfloat162 v = __floats2bfloat162_rn(lo, hi);
    return *(uint32_t*)&v;
}

__device__ __forceinline__ void mma_bf16(float c[4], const uint32_t a[4],
                                         uint32_t b0, uint32_t b1) {
    asm volatile(
        "mma.sync.aligned.m16n8k16.row.col.f32.bf16.bf16.f32 "
        "{%0,%1,%2,%3}, {%4,%5,%6,%7}, {%8,%9}, {%0,%1,%2,%3};"
        : "+f"(c[0]), "+f"(c[1]), "+f"(c[2]), "+f"(c[3])
        : "r"(a[0]), "r"(a[1]), "r"(a[2]), "r"(a[3]), "r"(b0), "r"(b1));
}

__device__ __forceinline__ void ldsm4(uint32_t& r0, uint32_t& r1, uint32_t& r2,
                                      uint32_t& r3, uint32_t addr) {
    asm volatile("ldmatrix.sync.aligned.m8n8.x4.shared.b16 {%0,%1,%2,%3}, [%4];"
                 : "=r"(r0), "=r"(r1), "=r"(r2), "=r"(r3) : "r"(addr));
}

__device__ __forceinline__ void cpa16(uint32_t dst, const void* src) {
    asm volatile("cp.async.cg.shared.global [%0], [%1], 16;\n"
                 :: "r"(dst), "l"(__cvta_generic_to_global(src)));
}

// ---------------- K0: fused prep (cvt_enc | cvt_wk | qw_partial) ---------------
__global__ void k_prep(const float* __restrict__ enc, const float* __restrict__ Wk,
                       const float* __restrict__ hidden, const float* __restrict__ Wq) {
    int b = blockIdx.x;
    int tid = threadIdx.x;
    if (b < 4096) {
        int idx = (b * 256 + tid) * 4;
        float4 v = *(const float4*)(enc + idx);
        uint2 o = make_uint2(pk(v.x, v.y), pk(v.z, v.w));
        *(uint2*)&g_encb[idx] = o;
    } else if (b < 4608) {
        int idx = (b - 4096) * 256 + tid;   // 0..131071
        int n = idx & 1023;
        int k2q = idx >> 10;
        uint4 o;
        const float* c = Wk + (size_t)(8 * k2q) * H + n;
        o.x = pk(c[0],     c[H]);
        o.y = pk(c[2 * H], c[3 * H]);
        o.z = pk(c[4 * H], c[5 * H]);
        o.w = pk(c[6 * H], c[7 * H]);
        *(uint4*)&g_wkbT[(size_t)n * 512 + k2q * 4] = o;
    } else {
        int r = b - 4608;                   // 0..127
        int j = (r & 3) * 256 + tid;
        int i0 = (r >> 2) * 32;
        const float* q = hidden + H;
        float acc = 0.f;
#pragma unroll
        for (int i = 0; i < 32; i++)
            acc += q[i0 + i] * Wq[(size_t)(i0 + i) * H + j];
        g_qwp[(r >> 2) * H + j] = acc;
    }
}

// ---------------- K3: attention GEMM (R13-proven: BK=32, 5-stage ring) ---------
// BM=128, BN=128; grid (8 bn, 32 bm); 8 warps = 2m x 4n; warp 64x32.
// smem BYTES: A stage s @ s*10240 (s=0..4) | B stage s @ 51200 + s*10240 |
//   sqw @102400 (512B) | swv @102912 (512B)  => total 103424
#define GEMM_SMEM_BYTES 103424
__global__ void __launch_bounds__(256, 2)
k_attn_gemm(const float* __restrict__ wv) {
    extern __shared__ uint32_t sm[];
    const int tid = threadIdx.x;
    const int warp = tid >> 5, lane = tid & 31;
    const int wm = warp & 1, wn = warp >> 1;     // 2 m x 4 n
    const int g = lane >> 2, t = lane & 3;
    const int bn = blockIdx.x, bm = blockIdx.y;

    float* sqw = (float*)((char*)sm + 102400);
    float* swv = (float*)((char*)sm + 102912);

    if (tid < 128) {
        int col = bn * 128 + tid;
        float s = 0.f;
#pragma unroll
        for (int p = 0; p < 32; p++) s += g_qwp[p * H + col];
        sqw[tid] = s;
        swv[tid] = wv[col];
    }

    float acc[4][4][4];
#pragma unroll
    for (int mt = 0; mt < 4; mt++)
#pragma unroll
        for (int nt = 0; nt < 4; nt++)
#pragma unroll
            for (int i = 0; i < 4; i++) acc[mt][nt][i] = 0.f;

    const int prow = tid >> 1, part = tid & 1;
    const __nv_bfloat16* Ag = g_encb + (size_t)(bm * 128 + prow) * H + part * 16;
    const uint32_t* Bg = g_wkbT + (size_t)(bn * 128 + prow) * 512 + part * 8;
    const uint32_t smBase = (uint32_t)__cvta_generic_to_shared(sm);
    const uint32_t aDst = smBase + (uint32_t)(prow * 20 + part * 8) * 4;
    const uint32_t bDst = smBase + 51200u + (uint32_t)(prow * 20 + part * 8) * 4;

#define LOAD_STAGE(it, st)                                               \
    {                                                                    \
        const uint32_t so = (uint32_t)(st) * 10240u;                     \
        const __nv_bfloat16* as_ = Ag + (size_t)(it) * 32;               \
        cpa16(aDst + so,      as_);                                      \
        cpa16(aDst + so + 16, as_ + 8);                                  \
        const uint32_t* bs_ = Bg + (size_t)(it) * 16;                    \
        cpa16(bDst + so,      bs_);                                      \
        cpa16(bDst + so + 16, bs_ + 4);                                  \
        asm volatile("cp.async.commit_group;");                          \
    }

    const uint32_t lrow = lane & 15, lcol = (lane >> 4) * 4;
    uint32_t aOff[4], bOff[2];
#pragma unroll
    for (int mt = 0; mt < 4; mt++)
        aOff[mt] = smBase + ((wm * 64 + mt * 16 + lrow) * 20 + lcol) * 4;
#pragma unroll
    for (int p = 0; p < 2; p++)
        bOff[p] = smBase + 51200u + ((wn * 32 + p * 16 + lrow) * 20 + lcol) * 4;

#define COMPUTE_STAGE(st)                                                \
    {                                                                    \
        const uint32_t so = (uint32_t)(st) * 10240u;                     \
        _Pragma("unroll")                                                \
        for (int ks = 0; ks < 2; ks++) {                                 \
            const uint32_t ko = so + (uint32_t)ks * 32u;                 \
            uint32_t a[4][4];                                            \
            _Pragma("unroll")                                            \
            for (int mt = 0; mt < 4; mt++)                               \
                ldsm4(a[mt][0], a[mt][1], a[mt][2], a[mt][3], aOff[mt] + ko); \
            _Pragma("unroll")                                            \
            for (int p = 0; p < 2; p++) {                                \
                uint32_t b0e, b0o, b1e, b1o;                             \
                ldsm4(b0e, b0o, b1e, b1o, bOff[p] + ko);                 \
                _Pragma("unroll")                                        \
                for (int mt = 0; mt < 4; mt++) {                         \
                    mma_bf16(acc[mt][2 * p],     a[mt], b0e, b1e);       \
                    mma_bf16(acc[mt][2 * p + 1], a[mt], b0o, b1o);       \
                }                                                        \
            }                                                            \
        }                                                                \
    }

    LOAD_STAGE(0, 0);
    LOAD_STAGE(1, 1);
    LOAD_STAGE(2, 2);
    LOAD_STAGE(3, 3);

    for (int base = 0; base < 25; base += 5) {
#pragma unroll
        for (int st = 0; st < 5; ++st) {
            const int it = base + st;
            asm volatile("cp.async.wait_group 3;");
            __syncthreads();
            LOAD_STAGE(it + 4, (st + 4) % 5);
            COMPUTE_STAGE(st);
        }
    }
    asm volatile("cp.async.wait_group 3;");
    __syncthreads();
    LOAD_STAGE(29, 4);
    COMPUTE_STAGE(0);
    asm volatile("cp.async.wait_group 3;");
    __syncthreads();
    LOAD_STAGE(30, 0);
    COMPUTE_STAGE(1);
    asm volatile("cp.async.wait_group 3;");
    __syncthreads();
    LOAD_STAGE(31, 1);
    COMPUTE_STAGE(2);
    asm volatile("cp.async.wait_group 3;");
    __syncthreads();
    COMPUTE_STAGE(3);
    asm volatile("cp.async.wait_group 2;");
    __syncthreads();
    COMPUTE_STAGE(4);
    asm volatile("cp.async.wait_group 1;");
    __syncthreads();
    COMPUTE_STAGE(0);
    asm volatile("cp.async.wait_group 0;");
    __syncthreads();
    COMPUTE_STAGE(1);

    float s[8];
#pragma unroll
    for (int i = 0; i < 8; i++) s[i] = 0.f;
#pragma unroll
    for (int mt = 0; mt < 4; mt++) {
#pragma unroll
        for (int nt = 0; nt < 4; nt++) {
            int lc = wn * 32 + nt * 8 + 2 * t;
            float qw0 = sqw[lc], qw1 = sqw[lc + 1];
            float w0 = swv[lc], w1 = swv[lc + 1];
            s[mt * 2 + 0] += tanhf(acc[mt][nt][0] + qw0) * w0 + tanhf(acc[mt][nt][1] + qw1) * w1;
            s[mt * 2 + 1] += tanhf(acc[mt][nt][2] + qw0) * w0 + tanhf(acc[mt][nt][3] + qw1) * w1;
        }
    }
#pragma unroll
    for (int i = 0; i < 8; i++) {
        s[i] += __shfl_xor_sync(0xffffffffu, s[i], 1);
        s[i] += __shfl_xor_sync(0xffffffffu, s[i], 2);
    }
    __syncthreads();
    float* red = (float*)sm;
    if (t == 0) {
#pragma unroll
        for (int mt = 0; mt < 4; mt++) {
            red[(wm * 64 + mt * 16 + g) * 4 + wn]     = s[2 * mt];
            red[(wm * 64 + mt * 16 + g + 8) * 4 + wn] = s[2 * mt + 1];
        }
    }
    __syncthreads();
    if (tid < 128) {
        float vsum = red[tid * 4] + red[tid * 4 + 1] + red[tid * 4 + 2] + red[tid * 4 + 3];
        g_scorep[(size_t)bn * L + bm * 128 + tid] = vsum;
    }
}

// ---------------- K5: ctx partials + FUSED softmax (grid 256, 256 thr) ---------
__global__ void k_ctx_partial() {
    __shared__ float se[32];
    int tid = threadIdx.x;
    int jhalf = blockIdx.x & 1;
    int lc = blockIdx.x >> 1;                 // 0..127
    int l0 = lc * 32;

    if (tid < 32) {
        float sc = 0.f;
#pragma unroll
        for (int p = 0; p < NPART; p++) sc += g_scorep[(size_t)p * L + l0 + tid];
        float e = expf(sc);
        se[tid] = e;
        float q = e;
#pragma unroll
        for (int o = 16; o > 0; o >>= 1) q += __shfl_xor_sync(0xffffffffu, q, o);
        if (tid == 0 && jhalf == 0) g_espart[lc] = q;
    }
    __syncthreads();

    int j0 = jhalf * 512 + tid * 2;
    float a0 = 0.f, a1 = 0.f;
#pragma unroll
    for (int l = 0; l < 32; l++) {
        float a = se[l];
        __nv_bfloat162 w = *(const __nv_bfloat162*)&g_encb[(size_t)(l0 + l) * H + j0];
        float2 f = __bfloat1622float2(w);
        a0 += a * f.x;
        a1 += a * f.y;
    }
    g_ctxp[lc * H + j0]     = a0;
    g_ctxp[lc * H + j0 + 1] = a1;
}

// ---------------- K6: x = concat(ctx/S, relu(emb[token])) -----------------------
// S computed cooperatively: 128 threads load one espart each, smem tree-reduce.
__global__ void k_build_x(const int* __restrict__ input, const float* __restrict__ emb) {
    __shared__ float sred[128];
    int tid = threadIdx.x;
    if (tid < 128) sred[tid] = g_espart[tid];
    __syncthreads();
    for (int o = 64; o > 0; o >>= 1) {
        if (tid < o) sred[tid] += sred[tid + o];
        __syncthreads();
    }
    float invS = 1.0f / sred[0];

    int idx = blockIdx.x * 256 + tid;
    if (idx < H) {
        float s0 = 0.f, s1 = 0.f, s2 = 0.f, s3 = 0.f;
#pragma unroll
        for (int p = 0; p < CTXP; p += 4) {
            s0 += g_ctxp[p * H + idx];
            s1 += g_ctxp[(p + 1) * H + idx];
            s2 += g_ctxp[(p + 2) * H + idx];
            s3 += g_ctxp[(p + 3) * H + idx];
        }
        g_x[idx] = (s0 + s1 + s2 + s3) * invS;
    } else {
        int tok = input[0];
        float e = emb[(size_t)tok * H + (idx - H)];
        g_x[idx] = fmaxf(e, 0.f);
    }
}

// ---------------- K7: GRU layer-0 GEMV ----------------
__global__ void k_gru_gemv0(const float* __restrict__ Wi, const float* __restrict__ Wh,
                            const float* __restrict__ bi, const float* __restrict__ bh,
                            const float* __restrict__ hidden) {
    __shared__ float sxh[X2 + H];
    int tid = threadIdx.x;
    for (int i = tid; i < X2; i += 256) sxh[i] = g_x[i];
    for (int i = tid; i < H; i += 256) sxh[X2 + i] = hidden[i];
    __syncthreads();

    int warp = blockIdx.x * 8 + (tid >> 5);
    int lane = tid & 31;
    if (warp < G3) {
        const float* W = Wi + (size_t)warp * X2;
        float acc = 0.f;
#pragma unroll
        for (int c0 = 0; c0 < X2; c0 += 128) {
            int c = c0 + lane * 4;
            float4 w = *(const float4*)(W + c);
            acc += w.x * sxh[c] + w.y * sxh[c + 1] + w.z * sxh[c + 2] + w.w * sxh[c + 3];
        }
#pragma unroll
        for (int o = 16; o > 0; o >>= 1) acc += __shfl_down_sync(0xffffffffu, acc, o);
        if (lane == 0) g_gi0[warp] = acc + bi[warp];
    } else {
        int r = warp - G3;
        const float* W = Wh + (size_t)r * H;
        float acc = 0.f;
#pragma unroll
        for (int c0 = 0; c0 < H; c0 += 128) {
            int c = c0 + lane * 4;
            float4 w = *(const float4*)(W + c);
            acc += w.x * sxh[X2 + c] + w.y * sxh[X2 + c + 1] + w.z * sxh[X2 + c + 2] + w.w * sxh[X2 + c + 3];
        }
#pragma unroll
        for (int o = 16; o > 0; o >>= 1) acc += __shfl_down_sync(0xffffffffu, acc, o);
        if (lane == 0) g_gh0[r] = acc + bh[r];
    }
}

// ---------------- K8: GRU layer-1 GEMV, fused layer-0 combine -------------------
__global__ void k_gru_gemv1(const float* __restrict__ Wi, const float* __restrict__ Wh,
                            const float* __restrict__ bi, const float* __restrict__ bh,
                            const float* __restrict__ hidden, float* __restrict__ out_h0) {
    __shared__ float sxh[2 * H];
    int tid = threadIdx.x;
    for (int i = tid; i < H; i += 256) {
        float r = sigmoidf_(g_gi0[i] + g_gh0[i]);
        float z = sigmoidf_(g_gi0[i + H] + g_gh0[i + H]);
        float n = tanhf(g_gi0[i + 2 * H] + r * g_gh0[i + 2 * H]);
        float hn = (1.0f - z) * n + z * hidden[i];
        sxh[i] = hn;
        if (blockIdx.x == 0) out_h0[i] = hn;
        sxh[H + i] = hidden[H + i];
    }
    __syncthreads();

    int warp = blockIdx.x * 8 + (tid >> 5);
    int lane = tid & 31;
    const float* W = (warp < G3) ? (Wi + (size_t)warp * H)
                                 : (Wh + (size_t)(warp - G3) * H);
    const float* xv = (warp < G3) ? sxh : (sxh + H);
    float acc = 0.f;
#pragma unroll
    for (int c0 = 0; c0 < H; c0 += 128) {
        int c = c0 + lane * 4;
        float4 w = *(const float4*)(W + c);
        acc += w.x * xv[c] + w.y * xv[c + 1] + w.z * xv[c + 2] + w.w * xv[c + 3];
    }
#pragma unroll
    for (int o = 16; o > 0; o >>= 1) acc += __shfl_down_sync(0xffffffffu, acc, o);
    if (lane == 0) {
        if (warp < G3) g_gi1[warp] = acc + bi[warp];
        else           g_gh1[warp - G3] = acc + bh[warp - G3];
    }
}

// ---------------- K9: split-K logits partials (grid 197 x 4) -------------------
__global__ void k_logits_part(const float* __restrict__ Wd, const float* __restrict__ bd,
                              const float* __restrict__ hidden, float* __restrict__ out_h1) {
    __shared__ float sh[256];
    int tid = threadIdx.x;
    int kp = blockIdx.y;
    int i = kp * 256 + tid;
    {
        float r = sigmoidf_(g_gi1[i] + g_gh1[i]);
        float z = sigmoidf_(g_gi1[i + H] + g_gh1[i + H]);
        float n = tanhf(g_gi1[i + 2 * H] + r * g_gh1[i + 2 * H]);
        float hn = (1.0f - z) * n + z * hidden[H + i];
        sh[tid] = hn;
        if (blockIdx.x == 0) out_h1[i] = hn;
    }
    __syncthreads();

    int v = blockIdx.x * 256 + tid;
    if (v < V) {
        float acc = (kp == 0) ? bd[v] : 0.f;
        const float* Wb = Wd + (size_t)(kp * 256) * V + v;
#pragma unroll 16
        for (int h = 0; h < 256; h++)
            acc += sh[h] * Wb[(size_t)h * V];
        g_logitp[kp * VP + v] = acc;
    }
}

// ---------------- K10: combine partials + softmax stats ------------------------
__global__ void k_logits_comb(float* __restrict__ out) {
    __shared__ float sred[256];
    int tid = threadIdx.x;
    int v = blockIdx.x * 256 + tid;
    float acc = -INFINITY;
    if (v < V) {
        acc = g_logitp[v] + g_logitp[VP + v] + g_logitp[2 * VP + v] + g_logitp[3 * VP + v];
        out[v] = acc;
    }
    sred[tid] = acc;
    __syncthreads();
    for (int o = 128; o > 0; o >>= 1) {
        if (tid < o) sred[tid] = fmaxf(sred[tid], sred[tid + o]);
        __syncthreads();
    }
    float bm = sred[0];
    __syncthreads();
    sred[tid] = (v < V) ? expf(acc - bm) : 0.f;
    __syncthreads();
    for (int o = 128; o > 0; o >>= 1) {
        if (tid < o) sred[tid] += sred[tid + o];
        __syncthreads();
    }
    if (tid == 0) {
        g_mpart[blockIdx.x] = bm;
        g_spart[blockIdx.x] = sred[0];
    }
}

// ---------------- K11: fused lse + final subtract (197 blocks) ------------------
__global__ void k_lse_final(float* __restrict__ out) {
    __shared__ float sm_[256];
    __shared__ float ss[256];
    int t = threadIdx.x;
    float m = (t < 197) ? g_mpart[t] : -INFINITY;
    sm_[t] = m;
    __syncthreads();
    for (int o = 128; o > 0; o >>= 1) {
        if (t < o) sm_[t] = fmaxf(sm_[t], sm_[t + o]);
        __syncthreads();
    }
    float M = sm_[0];
    float s = (t < 197) ? g_spart[t] * expf(g_mpart[t] - M) : 0.f;
    ss[t] = s;
    __syncthreads();
    for (int o = 128; o > 0; o >>= 1) {
        if (t < o) ss[t] += ss[t + o];
        __syncthreads();
    }
    float lse = M + logf(ss[0]);
    int v = blockIdx.x * 256 + t;
    if (v < V) out[v] = out[v] - lse;
}

// ---------------- launcher ----------------
extern "C" void kernel_launch(void* const* d_in, const int* in_sizes, int n_in,
                              void* d_out, int out_size) {
    const int*   input  = (const int*)d_in[0];
    const float* hidden = (const float*)d_in[1];
    const float* enc    = (const float*)d_in[2];
    const float* emb    = (const float*)d_in[3];
    const float* Wq     = (const float*)d_in[4];
    const float* Wk     = (const float*)d_in[5];
    const float* wv     = (const float*)d_in[6];
    const float* W_ih0  = (const float*)d_in[7];
    const float* W_hh0  = (const float*)d_in[8];
    const float* b_ih0  = (const float*)d_in[9];
    const float* b_hh0  = (const float*)d_in[10];
    const float* W_ih1  = (const float*)d_in[11];
    const float* W_hh1  = (const float*)d_in[12];
    const float* b_ih1  = (const float*)d_in[13];
    const float* b_hh1  = (const float*)d_in[14];
    const float* Wd     = (const float*)d_in[15];
    const float* bd     = (const float*)d_in[16];

    float* out = (float*)d_out;  // [0,V) logp ; [V,V+H) h0n ; [V+H,V+2H) h1n

    static int smem_set = 0;
    if (!smem_set) {
        cudaFuncSetAttribute(k_attn_gemm, cudaFuncAttributeMaxDynamicSharedMemorySize,
                             GEMM_SMEM_BYTES);
        smem_set = 1;
    }

    k_prep<<<4736, 256>>>(enc, Wk, hidden, Wq);
    k_attn_gemm<<<dim3(8, 32), 256, GEMM_SMEM_BYTES>>>(wv);
    k_ctx_partial<<<256, 256>>>();
    k_build_x<<<8, 256>>>(input, emb);
    k_gru_gemv0<<<768, 256>>>(W_ih0, W_hh0, b_ih0, b_hh0, hidden);
    k_gru_gemv1<<<768, 256>>>(W_ih1, W_hh1, b_ih1, b_hh1, hidden, out + V);
    k_logits_part<<<dim3(197, 4), 256>>>(Wd, bd, hidden, out + V + H);
    k_logits_comb<<<197, 256>>>(out);
    k_lse_final<<<197, 256>>>(out);
}